// round 14
// baseline (speedup 1.0000x reference)
#include <cuda_runtime.h>
#include <cuda_fp16.h>

#define N_MAX 50000
#define E_MAX 800000
#define F_IN 128
#define F_H  64
#define SCAN_B 256
#define SCAN_G ((N_MAX + SCAN_B - 1) / SCAN_B)   // 196

// Persistent scratch (no allocations allowed). g_degi and g_pack are
// self-restoring: every execution leaves them zeroed for the next replay.
__device__ int     g_degi  [N_MAX];
__device__ float   g_dinv  [N_MAX];
__device__ int     g_offs  [N_MAX + 1];
__device__ int     g_cursor[N_MAX];
__device__ unsigned long long g_pack[SCAN_G];  // lookback: (value<<2)|state
__device__ int     g_csr   [E_MAX];            // src indices grouped by dst
__device__ __half2 g_hh    [N_MAX * 32];       // h1 = x@W1 (UNSCALED), fp16
__device__ __half2 g_hh2   [N_MAX * 32];       // h2 = z1@W2 (UNSCALED), fp16
__device__ __half2 g_z1h   [N_MAX * 32];       // z1 = tanh(conv1), fp16

// ---------------------------------------------------------------------------
// Helpers
// ---------------------------------------------------------------------------
__device__ __forceinline__ float tanh_ap(float x) {
    float y;
    asm("tanh.approx.f32 %0, %1;" : "=f"(y) : "f"(x));
    return y;
}
__device__ __forceinline__ unsigned h2u(float lo, float hi) {
    __half2 h = __floats2half2_rn(lo, hi);
    return *(unsigned*)&h;
}
__device__ __forceinline__ void mma16816(float* c, unsigned a0, unsigned a1,
                                         unsigned a2, unsigned a3,
                                         unsigned b0, unsigned b1) {
    asm volatile(
        "mma.sync.aligned.m16n8k16.row.col.f32.f16.f16.f32 "
        "{%0,%1,%2,%3}, {%4,%5,%6,%7}, {%8,%9}, {%0,%1,%2,%3};"
        : "+f"(c[0]), "+f"(c[1]), "+f"(c[2]), "+f"(c[3])
        : "r"(a0), "r"(a1), "r"(a2), "r"(a3), "r"(b0), "r"(b1));
}

// ---------------------------------------------------------------------------
// CSR build (R11/R13-proven forms)
// ---------------------------------------------------------------------------
__global__ void k_count(const int* __restrict__ dst, int E) {
    int e = (blockIdx.x * blockDim.x + threadIdx.x) * 4;
    if (e + 3 < E) {
        int4 d = *(const int4*)(dst + e);
        atomicAdd(&g_degi[d.x], 1);
        atomicAdd(&g_degi[d.y], 1);
        atomicAdd(&g_degi[d.z], 1);
        atomicAdd(&g_degi[d.w], 1);
    } else {
        for (; e < E; e++) atomicAdd(&g_degi[dst[e]], 1);
    }
}

// Single-pass scan with decoupled lookback (flag+value in one 64-bit word).
// Also computes dinv, seeds cursor, and RE-ZEROS g_degi for the next replay.
__global__ void k_scan(int n, int E, int nb) {
    __shared__ int s[SCAN_B];
    __shared__ int s_pre;
    int t = threadIdx.x, b = blockIdx.x;
    int i = b * SCAN_B + t;
    int v = (i < n) ? g_degi[i] : 0;
    if (i < n) {
        g_dinv[i] = rsqrtf((float)v + 1.0f);  // +1 self-loop
        g_degi[i] = 0;                        // restore invariant
    }
    s[t] = v;
    __syncthreads();
#pragma unroll
    for (int off = 1; off < SCAN_B; off <<= 1) {
        int u = (t >= off) ? s[t - off] : 0;
        __syncthreads();
        s[t] += u;
        __syncthreads();
    }
    if (t == 0) {
        int total = s[SCAN_B - 1];
        if (b == 0) {
            atomicExch(&g_pack[0], ((unsigned long long)total << 2) | 2ULL);
            s_pre = 0;
        } else {
            atomicExch(&g_pack[b], ((unsigned long long)total << 2) | 1ULL);
            int run = 0;
            for (int p = b - 1; p >= 0;) {
                unsigned long long w;
                do { w = atomicAdd(&g_pack[p], 0ULL); } while ((w & 3ULL) == 0ULL);
                run += (int)(w >> 2);
                if ((w & 3ULL) == 2ULL) break;
                p--;
            }
            atomicExch(&g_pack[b],
                       ((unsigned long long)(run + total) << 2) | 2ULL);
            s_pre = run;
        }
    }
    __syncthreads();
    int pre = s_pre;
    if (i < n) {
        int o = s[t] - v + pre;
        g_offs[i] = o;
        g_cursor[i] = o;
    }
    if (b == 0 && t == 0) g_offs[n] = E;
}

// Fill CSR; also re-zeros g_pack for the next replay.
__global__ void k_fill(const int* __restrict__ src,
                       const int* __restrict__ dst, int E) {
    if (blockIdx.x == 0 && threadIdx.x < SCAN_G) g_pack[threadIdx.x] = 0ULL;
    int e = (blockIdx.x * blockDim.x + threadIdx.x) * 4;
    if (e + 3 < E) {
        int4 sv = *(const int4*)(src + e);
        int4 dv = *(const int4*)(dst + e);
        g_csr[atomicAdd(&g_cursor[dv.x], 1)] = sv.x;
        g_csr[atomicAdd(&g_cursor[dv.y], 1)] = sv.y;
        g_csr[atomicAdd(&g_cursor[dv.z], 1)] = sv.z;
        g_csr[atomicAdd(&g_cursor[dv.w], 1)] = sv.w;
    } else {
        for (; e < E; e++) {
            int pos = atomicAdd(&g_cursor[dst[e]], 1);
            g_csr[pos] = src[e];
        }
    }
}

// ---------------------------------------------------------------------------
// GEMM 1 (tensor core): h1 = x @ W1  (M=50000, N=64, K=128), fp16, UNSCALED.
// A-fragments loaded DIRECTLY from global x (float2 -> half2 per fragment;
// 8 fully-used 32B sectors per warp-load). No x staging phase, no barrier
// between x load and mma. Only W is staged (17.4 KB static smem).
// 64-node tiles; warp (rg,cg): rows rg*16..+16, cols cg*32..+32.
// ---------------------------------------------------------------------------
#define XPAD 136
__global__ void k_gemm1(const float* __restrict__ x,
                        const float* __restrict__ W, int n) {
    __shared__ __half Wt[64 * XPAD];   // Wt[n][k]

    int tid = threadIdx.x;
    const float4* wg = (const float4*)W;
    for (int i = tid; i < 128 * 16; i += 256) {
        int k = i >> 4;
        int n4 = (i & 15) * 4;
        float4 v = wg[(size_t)k * 16 + (i & 15)];
        Wt[(n4 + 0) * XPAD + k] = __float2half_rn(v.x);
        Wt[(n4 + 1) * XPAD + k] = __float2half_rn(v.y);
        Wt[(n4 + 2) * XPAD + k] = __float2half_rn(v.z);
        Wt[(n4 + 3) * XPAD + k] = __float2half_rn(v.w);
    }
    __syncthreads();

    int warp = tid >> 5, lane = tid & 31;
    int rg = warp & 3, cg = warp >> 2;
    int tq = lane >> 2;
    int tr = lane & 3;

    int nodeBase = blockIdx.x * 64;
    int rowA = nodeBase + rg * 16 + tq;    // fragment rows 0-7
    int rowB = rowA + 8;                   // fragment rows 8-15
    bool okA = rowA < n, okB = rowB < n;
    const float* xA = x + (size_t)rowA * F_IN;
    const float* xB = x + (size_t)rowB * F_IN;

    float c[4][4];
#pragma unroll
    for (int j = 0; j < 4; j++)
#pragma unroll
        for (int q = 0; q < 4; q++) c[j][q] = 0.0f;

#pragma unroll
    for (int ks = 0; ks < 8; ks++) {
        int kb = ks * 16 + 2 * tr;
        float2 z2 = make_float2(0.f, 0.f);
        float2 fa0 = okA ? *(const float2*)(xA + kb)     : z2;
        float2 fa2 = okA ? *(const float2*)(xA + kb + 8) : z2;
        float2 fb0 = okB ? *(const float2*)(xB + kb)     : z2;
        float2 fb2 = okB ? *(const float2*)(xB + kb + 8) : z2;
        unsigned a0 = h2u(fa0.x, fa0.y);   // (rowA, k..k+1)
        unsigned a1 = h2u(fb0.x, fb0.y);   // (rowB, k..k+1)
        unsigned a2 = h2u(fa2.x, fa2.y);   // (rowA, k+8..k+9)
        unsigned a3 = h2u(fb2.x, fb2.y);   // (rowB, k+8..k+9)
#pragma unroll
        for (int nc = 0; nc < 4; nc++) {
            const __half* wb = Wt + (cg * 32 + nc * 8 + tq) * XPAD + ks * 16 + 2 * tr;
            unsigned b0 = *(const unsigned*)(wb);
            unsigned b1 = *(const unsigned*)(wb + 8);
            mma16816(c[nc], a0, a1, a2, a3, b0, b1);
        }
    }

    if (okA) {
        __half2* outp = g_hh + (size_t)rowA * 32 + cg * 16 + tr;
#pragma unroll
        for (int nc = 0; nc < 4; nc++)
            outp[nc * 4] = __floats2half2_rn(c[nc][0], c[nc][1]);
    }
    if (okB) {
        __half2* outp = g_hh + (size_t)rowB * 32 + cg * 16 + tr;
#pragma unroll
        for (int nc = 0; nc < 4; nc++)
            outp[nc * 4] = __floats2half2_rn(c[nc][2], c[nc][3]);
    }
}

// ---------------------------------------------------------------------------
// Deferred-norm gather body (R11-proven):
//   acc = h[d]*dinv[d] + sum h[s]*dinv[s];  z = tanh(acc*dinv[d] + b)
// ---------------------------------------------------------------------------
__device__ __forceinline__ float2 gather_node(const __half2* __restrict__ hs,
                                              int node, int lane,
                                              float b_lo, float b_hi) {
    int beg = g_offs[node];
    int end = g_offs[node + 1];
    float dd = g_dinv[node];
    float2 hv = __half22float2(hs[(size_t)node * 32 + lane]);
    float2 acc = make_float2(hv.x * dd, hv.y * dd);

    int i = beg;
    for (; i + 8 <= end; i += 8) {
        int sN[8];
#pragma unroll
        for (int j = 0; j < 8; j++) sN[j] = __ldg(&g_csr[i + j]);
        float dsN[8];
        float2 vN[8];
#pragma unroll
        for (int j = 0; j < 8; j++) {
            dsN[j] = __ldg(&g_dinv[sN[j]]);
            vN[j] = __half22float2(hs[(size_t)sN[j] * 32 + lane]);
        }
#pragma unroll
        for (int j = 0; j < 8; j++) {
            acc.x = fmaf(vN[j].x, dsN[j], acc.x);
            acc.y = fmaf(vN[j].y, dsN[j], acc.y);
        }
    }
    for (; i < end; i++) {
        int s = __ldg(&g_csr[i]);
        float ds = __ldg(&g_dinv[s]);
        float2 v = __half22float2(hs[(size_t)s * 32 + lane]);
        acc.x = fmaf(v.x, ds, acc.x);
        acc.y = fmaf(v.y, ds, acc.y);
    }
    return make_float2(tanh_ap(fmaf(acc.x, dd, b_lo)),
                       tanh_ap(fmaf(acc.y, dd, b_hi)));
}

// ---------------------------------------------------------------------------
// Gather 1 (standalone, warp per node): g_hh -> z1 (fp16).
// ---------------------------------------------------------------------------
__global__ void k_gath1(const float* __restrict__ bias, int n) {
    int node = (blockIdx.x * blockDim.x + threadIdx.x) >> 5;
    int lane = threadIdx.x & 31;
    if (node >= n) return;
    float b_lo = __ldg(&bias[2 * lane]);
    float b_hi = __ldg(&bias[2 * lane + 1]);
    float2 z = gather_node(g_hh, node, lane, b_lo, b_hi);
    g_z1h[(size_t)node * 32 + lane] = __float22half2_rn(z);
}

// ---------------------------------------------------------------------------
// GEMM 2 (tensor core): h2 = z1 @ W2 (M=50000, N=64, K=64), UNSCALED.
// 64-node tiles; static smem 18432 B. (R13-proven)
// ---------------------------------------------------------------------------
#define ZPAD 72
__global__ void k_gemm2(const float* __restrict__ W, int n) {
    __shared__ __half ah[64 * ZPAD];
    __shared__ __half Wt[64 * ZPAD];   // Wt[n][k]

    int tid = threadIdx.x;
    int nodeBase = blockIdx.x * 64;

    for (int i = tid; i < 64 * 32; i += 256) {
        int r = i >> 5;
        int c = i & 31;
        int gn = nodeBase + r;
        __half2 v = (gn < n) ? g_z1h[(size_t)gn * 32 + c]
                             : __floats2half2_rn(0.f, 0.f);
        *(__half2*)(ah + r * ZPAD + 2 * c) = v;
    }
    const float4* wg = (const float4*)W;
    for (int i = tid; i < 64 * 16; i += 256) {
        int k = i >> 4;
        int n4 = (i & 15) * 4;
        float4 v = wg[(size_t)k * 16 + (i & 15)];
        Wt[(n4 + 0) * ZPAD + k] = __float2half_rn(v.x);
        Wt[(n4 + 1) * ZPAD + k] = __float2half_rn(v.y);
        Wt[(n4 + 2) * ZPAD + k] = __float2half_rn(v.z);
        Wt[(n4 + 3) * ZPAD + k] = __float2half_rn(v.w);
    }
    __syncthreads();

    int warp = tid >> 5, lane = tid & 31;
    int rg = warp & 3, cg = warp >> 2;
    int tq = lane >> 2;
    int tr = lane & 3;

    float c[4][4];
#pragma unroll
    for (int j = 0; j < 4; j++)
#pragma unroll
        for (int q = 0; q < 4; q++) c[j][q] = 0.0f;

    const __half* aw = ah + (rg * 16 + tq) * ZPAD;
#pragma unroll
    for (int ks = 0; ks < 4; ks++) {
        int base = ks * 16 + 2 * tr;
        unsigned a0 = *(const unsigned*)(aw + base);
        unsigned a1 = *(const unsigned*)(aw + 8 * ZPAD + base);
        unsigned a2 = *(const unsigned*)(aw + base + 8);
        unsigned a3 = *(const unsigned*)(aw + 8 * ZPAD + base + 8);
#pragma unroll
        for (int nc = 0; nc < 4; nc++) {
            const __half* wb = Wt + (cg * 32 + nc * 8 + tq) * ZPAD + base;
            unsigned b0 = *(const unsigned*)(wb);
            unsigned b1 = *(const unsigned*)(wb + 8);
            mma16816(c[nc], a0, a1, a2, a3, b0, b1);
        }
    }

    int nodeA = nodeBase + rg * 16 + tq;
    int nodeB = nodeA + 8;
    if (nodeA < n) {
        __half2* outp = g_hh2 + (size_t)nodeA * 32 + cg * 16 + tr;
#pragma unroll
        for (int nc = 0; nc < 4; nc++)
            outp[nc * 4] = __floats2half2_rn(c[nc][0], c[nc][1]);
    }
    if (nodeB < n) {
        __half2* outp = g_hh2 + (size_t)nodeB * 32 + cg * 16 + tr;
#pragma unroll
        for (int nc = 0; nc < 4; nc++)
            outp[nc * 4] = __floats2half2_rn(c[nc][2], c[nc][3]);
    }
}

// ---------------------------------------------------------------------------
// Fused gather2 + FC head (64-node tiles): removes the t2 round-trip.
//   t2 = tanh(dinv*(h2[d]*dinv[d] + sum h2[s]*dinv[s]) + b2) -> tT (smem)
//   t = tanh(t2 @ fw1 + fb1);  out = t @ fw2 + fb2
// smem 25.3 KB; ~5 blocks/SM => ~40 gather warps/SM.
// ---------------------------------------------------------------------------
__global__ void k_gfc(const float* __restrict__ bias,
                      const float* __restrict__ fw1, const float* __restrict__ fb1,
                      const float* __restrict__ fw2, const float* __restrict__ fb2,
                      float* __restrict__ out, int n) {
    __shared__ float W1s[F_H * 32];
    __shared__ float tT[64 * 66];
    __shared__ float W2s[32];
    __shared__ float b1s[32];

    int tid = threadIdx.x;
    int warp = tid >> 5, lane = tid & 31;
    for (int i = tid; i < F_H * 32; i += 256) W1s[i] = fw1[i];
    if (tid < 32) {
        W2s[tid] = fw2[tid];
        b1s[tid] = fb1[tid];
    }

    int nodeBase = blockIdx.x * 64;
    float b_lo = __ldg(&bias[2 * lane]);
    float b_hi = __ldg(&bias[2 * lane + 1]);

    // Phase A: gather 8 nodes per warp
    for (int j = 0; j < 8; j++) {
        int r = warp * 8 + j;
        int node = nodeBase + r;
        float2 z = make_float2(0.0f, 0.0f);
        if (node < n) z = gather_node(g_hh2, node, lane, b_lo, b_hi);
        ((float2*)(tT + r * 66))[lane] = z;
    }
    __syncthreads();

    // Phase B: FC. 4 threads per node, 8 hidden outputs each.
    int rloc = tid >> 2;
    int q = tid & 3;
    int node = nodeBase + rloc;

    float acc[8];
#pragma unroll
    for (int j = 0; j < 8; j++) acc[j] = 0.0f;

    const float* trow = tT + rloc * 66;
#pragma unroll 8
    for (int k = 0; k < F_H; k++) {
        float rv = trow[k];
        const float4* wr = (const float4*)(W1s + k * 32 + q * 8);
        float4 w0 = wr[0], w1 = wr[1];
        acc[0] = fmaf(rv, w0.x, acc[0]);
        acc[1] = fmaf(rv, w0.y, acc[1]);
        acc[2] = fmaf(rv, w0.z, acc[2]);
        acc[3] = fmaf(rv, w0.w, acc[3]);
        acc[4] = fmaf(rv, w1.x, acc[4]);
        acc[5] = fmaf(rv, w1.y, acc[5]);
        acc[6] = fmaf(rv, w1.z, acc[6]);
        acc[7] = fmaf(rv, w1.w, acc[7]);
    }

    float r = 0.0f;
#pragma unroll
    for (int j = 0; j < 8; j++)
        r = fmaf(tanh_ap(acc[j] + b1s[q * 8 + j]), W2s[q * 8 + j], r);
    r += __shfl_xor_sync(0xffffffff, r, 1);
    r += __shfl_xor_sync(0xffffffff, r, 2);

    if (q == 0 && node < n) out[node] = r + __ldg(&fb2[0]);
}

// ---------------------------------------------------------------------------
extern "C" void kernel_launch(void* const* d_in, const int* in_sizes, int n_in,
                              void* d_out, int out_size) {
    const float* x   = (const float*)d_in[0];
    const int*   ei  = (const int*)  d_in[1];
    const float* w1  = (const float*)d_in[2];
    const float* b1  = (const float*)d_in[3];
    const float* w2  = (const float*)d_in[4];
    const float* b2  = (const float*)d_in[5];
    const float* fw1 = (const float*)d_in[6];
    const float* fb1 = (const float*)d_in[7];
    const float* fw2 = (const float*)d_in[8];
    const float* fb2 = (const float*)d_in[9];

    int n = in_sizes[0] / F_IN;   // 50000
    int E = in_sizes[1] / 2;      // 800000
    const int* src = ei;
    const int* dst = ei + E;
    float* out = (float*)d_out;

    int nb = (n + SCAN_B - 1) / SCAN_B;   // 196
    int blocks64 = (n + 63) / 64;         // 782
    int gathBlocks = (n * 32 + 255) / 256;

    // Serial 7-launch pipeline (streams proven null twice -> removed).
    // Slot 4 (profiled) = gemm1: direct readout of the direct-A-load change.
    k_count<<<(E / 4 + 255) / 256, 256>>>(dst, E);
    k_scan <<<nb, SCAN_B>>>(n, E, nb);
    k_fill <<<(E / 4 + 255) / 256, 256>>>(src, dst, E);
    k_gemm1<<<blocks64, 256>>>(x, w1, n);
    k_gath1<<<gathBlocks, 256>>>(b1, n);
    k_gemm2<<<blocks64, 256>>>(w2, n);
    k_gfc  <<<blocks64, 256>>>(b2, fw1, fb1, fw2, fb2, out, n);
}

// round 15
// speedup vs baseline: 1.0024x; 1.0024x over previous
#include <cuda_runtime.h>
#include <cuda_fp16.h>

#define N_MAX 50000
#define E_MAX 800000
#define F_IN 128
#define F_H  64
#define SCAN_B 256
#define SCAN_G ((N_MAX + SCAN_B - 1) / SCAN_B)   // 196

// Persistent scratch (no allocations allowed). g_degi and g_pack are
// self-restoring: every execution leaves them zeroed for the next replay.
__device__ int     g_degi  [N_MAX];
__device__ float   g_dinv  [N_MAX];
__device__ int     g_offs  [N_MAX + 1];
__device__ int     g_cursor[N_MAX];
__device__ unsigned long long g_pack[SCAN_G];  // lookback: (value<<2)|state
__device__ int     g_csr   [E_MAX];            // src indices grouped by dst
__device__ __half2 g_hh    [N_MAX * 32];       // h1 = x@W1 (UNSCALED), fp16
__device__ __half2 g_hh2   [N_MAX * 32];       // h2 = z1@W2 (UNSCALED), fp16
__device__ __half2 g_z1h   [N_MAX * 32];       // z1 = tanh(conv1), fp16
__device__ float2  g_t2    [N_MAX * 32];       // t2 = tanh(conv2), fp32

// ---------------------------------------------------------------------------
// Helpers
// ---------------------------------------------------------------------------
__device__ __forceinline__ float tanh_ap(float x) {
    float y;
    asm("tanh.approx.f32 %0, %1;" : "=f"(y) : "f"(x));
    return y;
}
__device__ __forceinline__ void mma16816(float* c, unsigned a0, unsigned a1,
                                         unsigned a2, unsigned a3,
                                         unsigned b0, unsigned b1) {
    asm volatile(
        "mma.sync.aligned.m16n8k16.row.col.f32.f16.f16.f32 "
        "{%0,%1,%2,%3}, {%4,%5,%6,%7}, {%8,%9}, {%0,%1,%2,%3};"
        : "+f"(c[0]), "+f"(c[1]), "+f"(c[2]), "+f"(c[3])
        : "r"(a0), "r"(a1), "r"(a2), "r"(a3), "r"(b0), "r"(b1));
}

// ---------------------------------------------------------------------------
// CSR build (R11/R13-proven forms)
// ---------------------------------------------------------------------------
__global__ void k_count(const int* __restrict__ dst, int E) {
    int e = (blockIdx.x * blockDim.x + threadIdx.x) * 4;
    if (e + 3 < E) {
        int4 d = *(const int4*)(dst + e);
        atomicAdd(&g_degi[d.x], 1);
        atomicAdd(&g_degi[d.y], 1);
        atomicAdd(&g_degi[d.z], 1);
        atomicAdd(&g_degi[d.w], 1);
    } else {
        for (; e < E; e++) atomicAdd(&g_degi[dst[e]], 1);
    }
}

// Single-pass scan with decoupled lookback (flag+value in one 64-bit word).
// Also computes dinv, seeds cursor, and RE-ZEROS g_degi for the next replay.
__global__ void k_scan(int n, int E, int nb) {
    __shared__ int s[SCAN_B];
    __shared__ int s_pre;
    int t = threadIdx.x, b = blockIdx.x;
    int i = b * SCAN_B + t;
    int v = (i < n) ? g_degi[i] : 0;
    if (i < n) {
        g_dinv[i] = rsqrtf((float)v + 1.0f);  // +1 self-loop
        g_degi[i] = 0;                        // restore invariant
    }
    s[t] = v;
    __syncthreads();
#pragma unroll
    for (int off = 1; off < SCAN_B; off <<= 1) {
        int u = (t >= off) ? s[t - off] : 0;
        __syncthreads();
        s[t] += u;
        __syncthreads();
    }
    if (t == 0) {
        int total = s[SCAN_B - 1];
        if (b == 0) {
            atomicExch(&g_pack[0], ((unsigned long long)total << 2) | 2ULL);
            s_pre = 0;
        } else {
            atomicExch(&g_pack[b], ((unsigned long long)total << 2) | 1ULL);
            int run = 0;
            for (int p = b - 1; p >= 0;) {
                unsigned long long w;
                do { w = atomicAdd(&g_pack[p], 0ULL); } while ((w & 3ULL) == 0ULL);
                run += (int)(w >> 2);
                if ((w & 3ULL) == 2ULL) break;
                p--;
            }
            atomicExch(&g_pack[b],
                       ((unsigned long long)(run + total) << 2) | 2ULL);
            s_pre = run;
        }
    }
    __syncthreads();
    int pre = s_pre;
    if (i < n) {
        int o = s[t] - v + pre;
        g_offs[i] = o;
        g_cursor[i] = o;
    }
    if (b == 0 && t == 0) g_offs[n] = E;
}

// Fill CSR; also re-zeros g_pack for the next replay.
__global__ void k_fill(const int* __restrict__ src,
                       const int* __restrict__ dst, int E) {
    if (blockIdx.x == 0 && threadIdx.x < SCAN_G) g_pack[threadIdx.x] = 0ULL;
    int e = (blockIdx.x * blockDim.x + threadIdx.x) * 4;
    if (e + 3 < E) {
        int4 sv = *(const int4*)(src + e);
        int4 dv = *(const int4*)(dst + e);
        g_csr[atomicAdd(&g_cursor[dv.x], 1)] = sv.x;
        g_csr[atomicAdd(&g_cursor[dv.y], 1)] = sv.y;
        g_csr[atomicAdd(&g_cursor[dv.z], 1)] = sv.z;
        g_csr[atomicAdd(&g_cursor[dv.w], 1)] = sv.w;
    } else {
        for (; e < E; e++) {
            int pos = atomicAdd(&g_cursor[dst[e]], 1);
            g_csr[pos] = src[e];
        }
    }
}

// ---------------------------------------------------------------------------
// GEMM 1 (tensor core): h1 = x @ W1  (M=50000, N=64, K=128), fp16, UNSCALED.
// R13-proven: 64-node tiles, x staged via LDG.128->smem, 34.8 KB static smem.
// ---------------------------------------------------------------------------
#define XPAD 136
__global__ void k_gemm1(const float* __restrict__ x,
                        const float* __restrict__ W, int n) {
    __shared__ __half xh[64 * XPAD];
    __shared__ __half Wt[64 * XPAD];   // Wt[n][k]

    int tid = threadIdx.x;
    int nodeBase = blockIdx.x * 64;

    const float4* xg = (const float4*)x;
    for (int i = tid; i < 64 * 32; i += 256) {
        int r = i >> 5;
        int c4 = (i & 31) * 4;
        int gn = nodeBase + r;
        float4 v = (gn < n) ? xg[(size_t)gn * 32 + (i & 31)]
                            : make_float4(0.f, 0.f, 0.f, 0.f);
        __half2* dstp = (__half2*)(xh + r * XPAD + c4);
        dstp[0] = __floats2half2_rn(v.x, v.y);
        dstp[1] = __floats2half2_rn(v.z, v.w);
    }
    const float4* wg = (const float4*)W;
    for (int i = tid; i < 128 * 16; i += 256) {
        int k = i >> 4;
        int n4 = (i & 15) * 4;
        float4 v = wg[(size_t)k * 16 + (i & 15)];
        Wt[(n4 + 0) * XPAD + k] = __float2half_rn(v.x);
        Wt[(n4 + 1) * XPAD + k] = __float2half_rn(v.y);
        Wt[(n4 + 2) * XPAD + k] = __float2half_rn(v.z);
        Wt[(n4 + 3) * XPAD + k] = __float2half_rn(v.w);
    }
    __syncthreads();

    int warp = tid >> 5, lane = tid & 31;
    int rg = warp & 3, cg = warp >> 2;
    int tq = lane >> 2;
    int tr = lane & 3;

    float c[4][4];
#pragma unroll
    for (int j = 0; j < 4; j++)
#pragma unroll
        for (int q = 0; q < 4; q++) c[j][q] = 0.0f;

    const __half* aw = xh + (rg * 16 + tq) * XPAD;
#pragma unroll
    for (int ks = 0; ks < 8; ks++) {
        int base = ks * 16 + 2 * tr;
        unsigned a0 = *(const unsigned*)(aw + base);
        unsigned a1 = *(const unsigned*)(aw + 8 * XPAD + base);
        unsigned a2 = *(const unsigned*)(aw + base + 8);
        unsigned a3 = *(const unsigned*)(aw + 8 * XPAD + base + 8);
#pragma unroll
        for (int nc = 0; nc < 4; nc++) {
            const __half* wb = Wt + (cg * 32 + nc * 8 + tq) * XPAD + base;
            unsigned b0 = *(const unsigned*)(wb);
            unsigned b1 = *(const unsigned*)(wb + 8);
            mma16816(c[nc], a0, a1, a2, a3, b0, b1);
        }
    }

    int nodeA = nodeBase + rg * 16 + tq;
    int nodeB = nodeA + 8;
    if (nodeA < n) {
        __half2* outp = g_hh + (size_t)nodeA * 32 + cg * 16 + tr;
#pragma unroll
        for (int nc = 0; nc < 4; nc++)
            outp[nc * 4] = __floats2half2_rn(c[nc][0], c[nc][1]);
    }
    if (nodeB < n) {
        __half2* outp = g_hh + (size_t)nodeB * 32 + cg * 16 + tr;
#pragma unroll
        for (int nc = 0; nc < 4; nc++)
            outp[nc * 4] = __floats2half2_rn(c[nc][2], c[nc][3]);
    }
}

// ---------------------------------------------------------------------------
// Deferred-norm gather body. NEW: csr indices read as broadcast int4 (2 LDGs
// per 8-edge batch instead of 8); scalar prologue aligns i to 4.
//   acc = h[d]*dinv[d] + sum h[s]*dinv[s];  z = tanh(acc*dinv[d] + b)
// ---------------------------------------------------------------------------
__device__ __forceinline__ void gather_edge(const __half2* __restrict__ hs,
                                            int s, int lane, float2& acc) {
    float ds = __ldg(&g_dinv[s]);
    float2 v = __half22float2(hs[(size_t)s * 32 + lane]);
    acc.x = fmaf(v.x, ds, acc.x);
    acc.y = fmaf(v.y, ds, acc.y);
}

__device__ __forceinline__ float2 gather_node(const __half2* __restrict__ hs,
                                              int node, int lane,
                                              float b_lo, float b_hi) {
    int beg = g_offs[node];
    int end = g_offs[node + 1];
    float dd = g_dinv[node];
    float2 hv = __half22float2(hs[(size_t)node * 32 + lane]);
    float2 acc = make_float2(hv.x * dd, hv.y * dd);

    int i = beg;
    // scalar prologue to 4-aligned index
    while (i < end && (i & 3)) {
        gather_edge(hs, __ldg(&g_csr[i]), lane, acc);
        i++;
    }
    // 8-edge batches via two broadcast int4 loads
    for (; i + 8 <= end; i += 8) {
        int4 c0 = __ldg((const int4*)(g_csr + i));
        int4 c1 = __ldg((const int4*)(g_csr + i + 4));
        int sN[8] = {c0.x, c0.y, c0.z, c0.w, c1.x, c1.y, c1.z, c1.w};
        float dsN[8];
        float2 vN[8];
#pragma unroll
        for (int j = 0; j < 8; j++) {
            dsN[j] = __ldg(&g_dinv[sN[j]]);
            vN[j] = __half22float2(hs[(size_t)sN[j] * 32 + lane]);
        }
#pragma unroll
        for (int j = 0; j < 8; j++) {
            acc.x = fmaf(vN[j].x, dsN[j], acc.x);
            acc.y = fmaf(vN[j].y, dsN[j], acc.y);
        }
    }
    // 4-edge batch
    if (i + 4 <= end) {
        int4 c0 = __ldg((const int4*)(g_csr + i));
        int sN[4] = {c0.x, c0.y, c0.z, c0.w};
        float dsN[4];
        float2 vN[4];
#pragma unroll
        for (int j = 0; j < 4; j++) {
            dsN[j] = __ldg(&g_dinv[sN[j]]);
            vN[j] = __half22float2(hs[(size_t)sN[j] * 32 + lane]);
        }
#pragma unroll
        for (int j = 0; j < 4; j++) {
            acc.x = fmaf(vN[j].x, dsN[j], acc.x);
            acc.y = fmaf(vN[j].y, dsN[j], acc.y);
        }
        i += 4;
    }
    // scalar tail
    for (; i < end; i++)
        gather_edge(hs, __ldg(&g_csr[i]), lane, acc);

    return make_float2(tanh_ap(fmaf(acc.x, dd, b_lo)),
                       tanh_ap(fmaf(acc.y, dd, b_hi)));
}

// ---------------------------------------------------------------------------
// Standalone gather kernels, one warp per node (R11/R13-proven shells).
// ---------------------------------------------------------------------------
__global__ void k_gath1(const float* __restrict__ bias, int n) {
    int node = (blockIdx.x * blockDim.x + threadIdx.x) >> 5;
    int lane = threadIdx.x & 31;
    if (node >= n) return;
    float b_lo = __ldg(&bias[2 * lane]);
    float b_hi = __ldg(&bias[2 * lane + 1]);
    float2 z = gather_node(g_hh, node, lane, b_lo, b_hi);
    g_z1h[(size_t)node * 32 + lane] = __float22half2_rn(z);
}

__global__ void k_gath2(const float* __restrict__ bias, int n) {
    int node = (blockIdx.x * blockDim.x + threadIdx.x) >> 5;
    int lane = threadIdx.x & 31;
    if (node >= n) return;
    float b_lo = __ldg(&bias[2 * lane]);
    float b_hi = __ldg(&bias[2 * lane + 1]);
    float2 z = gather_node(g_hh2, node, lane, b_lo, b_hi);
    g_t2[(size_t)node * 32 + lane] = z;
}

// ---------------------------------------------------------------------------
// GEMM 2 (tensor core): h2 = z1 @ W2 (M=50000, N=64, K=64), UNSCALED.
// 64-node tiles; static smem 18432 B. (R13-proven)
// ---------------------------------------------------------------------------
#define ZPAD 72
__global__ void k_gemm2(const float* __restrict__ W, int n) {
    __shared__ __half ah[64 * ZPAD];
    __shared__ __half Wt[64 * ZPAD];   // Wt[n][k]

    int tid = threadIdx.x;
    int nodeBase = blockIdx.x * 64;

    for (int i = tid; i < 64 * 32; i += 256) {
        int r = i >> 5;
        int c = i & 31;
        int gn = nodeBase + r;
        __half2 v = (gn < n) ? g_z1h[(size_t)gn * 32 + c]
                             : __floats2half2_rn(0.f, 0.f);
        *(__half2*)(ah + r * ZPAD + 2 * c) = v;
    }
    const float4* wg = (const float4*)W;
    for (int i = tid; i < 64 * 16; i += 256) {
        int k = i >> 4;
        int n4 = (i & 15) * 4;
        float4 v = wg[(size_t)k * 16 + (i & 15)];
        Wt[(n4 + 0) * ZPAD + k] = __float2half_rn(v.x);
        Wt[(n4 + 1) * ZPAD + k] = __float2half_rn(v.y);
        Wt[(n4 + 2) * ZPAD + k] = __float2half_rn(v.z);
        Wt[(n4 + 3) * ZPAD + k] = __float2half_rn(v.w);
    }
    __syncthreads();

    int warp = tid >> 5, lane = tid & 31;
    int rg = warp & 3, cg = warp >> 2;
    int tq = lane >> 2;
    int tr = lane & 3;

    float c[4][4];
#pragma unroll
    for (int j = 0; j < 4; j++)
#pragma unroll
        for (int q = 0; q < 4; q++) c[j][q] = 0.0f;

    const __half* aw = ah + (rg * 16 + tq) * ZPAD;
#pragma unroll
    for (int ks = 0; ks < 4; ks++) {
        int base = ks * 16 + 2 * tr;
        unsigned a0 = *(const unsigned*)(aw + base);
        unsigned a1 = *(const unsigned*)(aw + 8 * ZPAD + base);
        unsigned a2 = *(const unsigned*)(aw + base + 8);
        unsigned a3 = *(const unsigned*)(aw + 8 * ZPAD + base + 8);
#pragma unroll
        for (int nc = 0; nc < 4; nc++) {
            const __half* wb = Wt + (cg * 32 + nc * 8 + tq) * ZPAD + base;
            unsigned b0 = *(const unsigned*)(wb);
            unsigned b1 = *(const unsigned*)(wb + 8);
            mma16816(c[nc], a0, a1, a2, a3, b0, b1);
        }
    }

    int nodeA = nodeBase + rg * 16 + tq;
    int nodeB = nodeA + 8;
    if (nodeA < n) {
        __half2* outp = g_hh2 + (size_t)nodeA * 32 + cg * 16 + tr;
#pragma unroll
        for (int nc = 0; nc < 4; nc++)
            outp[nc * 4] = __floats2half2_rn(c[nc][0], c[nc][1]);
    }
    if (nodeB < n) {
        __half2* outp = g_hh2 + (size_t)nodeB * 32 + cg * 16 + tr;
#pragma unroll
        for (int nc = 0; nc < 4; nc++)
            outp[nc * 4] = __floats2half2_rn(c[nc][2], c[nc][3]);
    }
}

// ---------------------------------------------------------------------------
// FC head: t2 (fp32, gmem) -> t = tanh(t2 @ fw1 + fb1) -> out = t@fw2 + fb2.
// (R13-proven)
// ---------------------------------------------------------------------------
__global__ void k_fc(const float* __restrict__ fw1, const float* __restrict__ fb1,
                     const float* __restrict__ fw2, const float* __restrict__ fb2,
                     float* __restrict__ out, int n) {
    __shared__ float W1s[F_H * 32];
    __shared__ float tT[64 * 66];
    __shared__ float W2s[32];
    __shared__ float b1s[32];

    int tid = threadIdx.x;
    for (int i = tid; i < F_H * 32; i += 256) W1s[i] = fw1[i];
    if (tid < 32) {
        W2s[tid] = fw2[tid];
        b1s[tid] = fb1[tid];
    }

    int nodeBase = blockIdx.x * 64;
    for (int i = tid; i < 64 * 32; i += 256) {
        int r = i >> 5;
        int c = i & 31;
        int gn = nodeBase + r;
        float2 v = (gn < n) ? g_t2[(size_t)gn * 32 + c] : make_float2(0.f, 0.f);
        ((float2*)(tT + r * 66))[c] = v;
    }
    __syncthreads();

    int rloc = tid >> 2;
    int q = tid & 3;
    int node = nodeBase + rloc;

    float acc[8];
#pragma unroll
    for (int j = 0; j < 8; j++) acc[j] = 0.0f;

    const float* trow = tT + rloc * 66;
#pragma unroll 8
    for (int k = 0; k < F_H; k++) {
        float rv = trow[k];
        const float4* wr = (const float4*)(W1s + k * 32 + q * 8);
        float4 w0 = wr[0], w1 = wr[1];
        acc[0] = fmaf(rv, w0.x, acc[0]);
        acc[1] = fmaf(rv, w0.y, acc[1]);
        acc[2] = fmaf(rv, w0.z, acc[2]);
        acc[3] = fmaf(rv, w0.w, acc[3]);
        acc[4] = fmaf(rv, w1.x, acc[4]);
        acc[5] = fmaf(rv, w1.y, acc[5]);
        acc[6] = fmaf(rv, w1.z, acc[6]);
        acc[7] = fmaf(rv, w1.w, acc[7]);
    }

    float r = 0.0f;
#pragma unroll
    for (int j = 0; j < 8; j++)
        r = fmaf(tanh_ap(acc[j] + b1s[q * 8 + j]), W2s[q * 8 + j], r);
    r += __shfl_xor_sync(0xffffffff, r, 1);
    r += __shfl_xor_sync(0xffffffff, r, 2);

    if (q == 0 && node < n) out[node] = r + __ldg(&fb2[0]);
}

// ---------------------------------------------------------------------------
extern "C" void kernel_launch(void* const* d_in, const int* in_sizes, int n_in,
                              void* d_out, int out_size) {
    const float* x   = (const float*)d_in[0];
    const int*   ei  = (const int*)  d_in[1];
    const float* w1  = (const float*)d_in[2];
    const float* b1  = (const float*)d_in[3];
    const float* w2  = (const float*)d_in[4];
    const float* b2  = (const float*)d_in[5];
    const float* fw1 = (const float*)d_in[6];
    const float* fb1 = (const float*)d_in[7];
    const float* fw2 = (const float*)d_in[8];
    const float* fb2 = (const float*)d_in[9];

    int n = in_sizes[0] / F_IN;   // 50000
    int E = in_sizes[1] / 2;      // 800000
    const int* src = ei;
    const int* dst = ei + E;
    float* out = (float*)d_out;

    int nb = (n + SCAN_B - 1) / SCAN_B;   // 196
    int blocks64 = (n + 63) / 64;         // 782
    int gathBlocks = (n * 32 + 255) / 256;

    // Serial 8-launch pipeline (R13 config minus the null stream machinery).
    // Slot 4 (profiled) = gemm1: expect ~19.7us (revert confirmation).
    k_count<<<(E / 4 + 255) / 256, 256>>>(dst, E);
    k_scan <<<nb, SCAN_B>>>(n, E, nb);
    k_fill <<<(E / 4 + 255) / 256, 256>>>(src, dst, E);
    k_gemm1<<<blocks64, 256>>>(x, w1, n);
    k_gath1<<<gathBlocks, 256>>>(b1, n);
    k_gemm2<<<blocks64, 256>>>(w2, n);
    k_gath2<<<gathBlocks, 256>>>(b2, n);
    k_fc   <<<blocks64, 256>>>(fw1, fb1, fw2, fb2, out, n);
}

// round 16
// speedup vs baseline: 1.0871x; 1.0846x over previous
#include <cuda_runtime.h>
#include <cuda_fp16.h>

#define N_MAX 50000
#define E_MAX 800000
#define F_IN 128
#define F_H  64
#define SCAN_B 256
#define SCAN_G ((N_MAX + SCAN_B - 1) / SCAN_B)   // 196

// Persistent scratch (no allocations allowed). g_degi and g_pack are
// self-restoring: every execution leaves them zeroed for the next replay.
__device__ int     g_degi  [N_MAX];
__device__ float   g_dinv  [N_MAX];
__device__ int     g_offs  [N_MAX + 1];
__device__ int     g_rank  [E_MAX];            // per-edge rank in dst bucket
__device__ unsigned long long g_pack[SCAN_G];  // lookback: (value<<2)|state
__device__ int     g_csr   [E_MAX];            // src indices grouped by dst
__device__ __half2 g_hh    [N_MAX * 32];       // h1 = x@W1 (UNSCALED), fp16
__device__ __half2 g_hh2   [N_MAX * 32];       // h2 = z1@W2 (UNSCALED), fp16
__device__ __half2 g_z1h   [N_MAX * 32];       // z1 = tanh(conv1), fp16
__device__ float2  g_t2    [N_MAX * 32];       // t2 = tanh(conv2), fp32

// ---------------------------------------------------------------------------
// Helpers
// ---------------------------------------------------------------------------
__device__ __forceinline__ float tanh_ap(float x) {
    float y;
    asm("tanh.approx.f32 %0, %1;" : "=f"(y) : "f"(x));
    return y;
}
__device__ __forceinline__ void mma16816(float* c, unsigned a0, unsigned a1,
                                         unsigned a2, unsigned a3,
                                         unsigned b0, unsigned b1) {
    asm volatile(
        "mma.sync.aligned.m16n8k16.row.col.f32.f16.f16.f32 "
        "{%0,%1,%2,%3}, {%4,%5,%6,%7}, {%8,%9}, {%0,%1,%2,%3};"
        : "+f"(c[0]), "+f"(c[1]), "+f"(c[2]), "+f"(c[3])
        : "r"(a0), "r"(a1), "r"(a2), "r"(a3), "r"(b0), "r"(b1));
}

// ---------------------------------------------------------------------------
// CSR build. NEW: k_count captures each edge's rank within its dst bucket
// (the atomic return we previously threw away); k_fill is then atomic-free.
// ---------------------------------------------------------------------------
__global__ void k_count(const int* __restrict__ dst, int E) {
    int e = (blockIdx.x * blockDim.x + threadIdx.x) * 4;
    if (e + 3 < E) {
        int4 d = *(const int4*)(dst + e);
        int4 r;
        r.x = atomicAdd(&g_degi[d.x], 1);
        r.y = atomicAdd(&g_degi[d.y], 1);
        r.z = atomicAdd(&g_degi[d.z], 1);
        r.w = atomicAdd(&g_degi[d.w], 1);
        *(int4*)(g_rank + e) = r;   // e-indexed store: address independent
    } else {
        for (; e < E; e++) g_rank[e] = atomicAdd(&g_degi[dst[e]], 1);
    }
}

// Single-pass scan with decoupled lookback (flag+value in one 64-bit word).
// Also computes dinv and RE-ZEROS g_degi for the next replay.
__global__ void k_scan(int n, int E, int nb) {
    __shared__ int s[SCAN_B];
    __shared__ int s_pre;
    int t = threadIdx.x, b = blockIdx.x;
    int i = b * SCAN_B + t;
    int v = (i < n) ? g_degi[i] : 0;
    if (i < n) {
        g_dinv[i] = rsqrtf((float)v + 1.0f);  // +1 self-loop
        g_degi[i] = 0;                        // restore invariant
    }
    s[t] = v;
    __syncthreads();
#pragma unroll
    for (int off = 1; off < SCAN_B; off <<= 1) {
        int u = (t >= off) ? s[t - off] : 0;
        __syncthreads();
        s[t] += u;
        __syncthreads();
    }
    if (t == 0) {
        int total = s[SCAN_B - 1];
        if (b == 0) {
            atomicExch(&g_pack[0], ((unsigned long long)total << 2) | 2ULL);
            s_pre = 0;
        } else {
            atomicExch(&g_pack[b], ((unsigned long long)total << 2) | 1ULL);
            int run = 0;
            for (int p = b - 1; p >= 0;) {
                unsigned long long w;
                do { w = atomicAdd(&g_pack[p], 0ULL); } while ((w & 3ULL) == 0ULL);
                run += (int)(w >> 2);
                if ((w & 3ULL) == 2ULL) break;
                p--;
            }
            atomicExch(&g_pack[b],
                       ((unsigned long long)(run + total) << 2) | 2ULL);
            s_pre = run;
        }
    }
    __syncthreads();
    int pre = s_pre;
    if (i < n) g_offs[i] = s[t] - v + pre;
    if (b == 0 && t == 0) g_offs[n] = E;
}

// Fill CSR — ATOMIC-FREE: position = offs[dst] + rank. Pure streaming.
// Also re-zeros g_pack for the next replay.
__global__ void k_fill(const int* __restrict__ src,
                       const int* __restrict__ dst, int E) {
    if (blockIdx.x == 0 && threadIdx.x < SCAN_G) g_pack[threadIdx.x] = 0ULL;
    int e = (blockIdx.x * blockDim.x + threadIdx.x) * 4;
    if (e + 3 < E) {
        int4 sv = *(const int4*)(src + e);
        int4 dv = *(const int4*)(dst + e);
        int4 rv = *(const int4*)(g_rank + e);
        g_csr[__ldg(&g_offs[dv.x]) + rv.x] = sv.x;
        g_csr[__ldg(&g_offs[dv.y]) + rv.y] = sv.y;
        g_csr[__ldg(&g_offs[dv.z]) + rv.z] = sv.z;
        g_csr[__ldg(&g_offs[dv.w]) + rv.w] = sv.w;
    } else {
        for (; e < E; e++)
            g_csr[__ldg(&g_offs[dst[e]]) + g_rank[e]] = src[e];
    }
}

// ---------------------------------------------------------------------------
// GEMM 1 (tensor core): h1 = x @ W1  (M=50000, N=64, K=128), fp16, UNSCALED.
// R13-proven: 64-node tiles, x staged via LDG.128->smem, 34.8 KB static smem.
// No CSR dependency -> side stream (R13-measured ~3us win).
// ---------------------------------------------------------------------------
#define XPAD 136
__global__ void k_gemm1(const float* __restrict__ x,
                        const float* __restrict__ W, int n) {
    __shared__ __half xh[64 * XPAD];
    __shared__ __half Wt[64 * XPAD];   // Wt[n][k]

    int tid = threadIdx.x;
    int nodeBase = blockIdx.x * 64;

    const float4* xg = (const float4*)x;
    for (int i = tid; i < 64 * 32; i += 256) {
        int r = i >> 5;
        int c4 = (i & 31) * 4;
        int gn = nodeBase + r;
        float4 v = (gn < n) ? xg[(size_t)gn * 32 + (i & 31)]
                            : make_float4(0.f, 0.f, 0.f, 0.f);
        __half2* dstp = (__half2*)(xh + r * XPAD + c4);
        dstp[0] = __floats2half2_rn(v.x, v.y);
        dstp[1] = __floats2half2_rn(v.z, v.w);
    }
    const float4* wg = (const float4*)W;
    for (int i = tid; i < 128 * 16; i += 256) {
        int k = i >> 4;
        int n4 = (i & 15) * 4;
        float4 v = wg[(size_t)k * 16 + (i & 15)];
        Wt[(n4 + 0) * XPAD + k] = __float2half_rn(v.x);
        Wt[(n4 + 1) * XPAD + k] = __float2half_rn(v.y);
        Wt[(n4 + 2) * XPAD + k] = __float2half_rn(v.z);
        Wt[(n4 + 3) * XPAD + k] = __float2half_rn(v.w);
    }
    __syncthreads();

    int warp = tid >> 5, lane = tid & 31;
    int rg = warp & 3, cg = warp >> 2;
    int tq = lane >> 2;
    int tr = lane & 3;

    float c[4][4];
#pragma unroll
    for (int j = 0; j < 4; j++)
#pragma unroll
        for (int q = 0; q < 4; q++) c[j][q] = 0.0f;

    const __half* aw = xh + (rg * 16 + tq) * XPAD;
#pragma unroll
    for (int ks = 0; ks < 8; ks++) {
        int base = ks * 16 + 2 * tr;
        unsigned a0 = *(const unsigned*)(aw + base);
        unsigned a1 = *(const unsigned*)(aw + 8 * XPAD + base);
        unsigned a2 = *(const unsigned*)(aw + base + 8);
        unsigned a3 = *(const unsigned*)(aw + 8 * XPAD + base + 8);
#pragma unroll
        for (int nc = 0; nc < 4; nc++) {
            const __half* wb = Wt + (cg * 32 + nc * 8 + tq) * XPAD + base;
            unsigned b0 = *(const unsigned*)(wb);
            unsigned b1 = *(const unsigned*)(wb + 8);
            mma16816(c[nc], a0, a1, a2, a3, b0, b1);
        }
    }

    int nodeA = nodeBase + rg * 16 + tq;
    int nodeB = nodeA + 8;
    if (nodeA < n) {
        __half2* outp = g_hh + (size_t)nodeA * 32 + cg * 16 + tr;
#pragma unroll
        for (int nc = 0; nc < 4; nc++)
            outp[nc * 4] = __floats2half2_rn(c[nc][0], c[nc][1]);
    }
    if (nodeB < n) {
        __half2* outp = g_hh + (size_t)nodeB * 32 + cg * 16 + tr;
#pragma unroll
        for (int nc = 0; nc < 4; nc++)
            outp[nc * 4] = __floats2half2_rn(c[nc][2], c[nc][3]);
    }
}

// ---------------------------------------------------------------------------
// Deferred-norm gather body (R11/R13-proven scalar-csr 8-unroll form):
//   acc = h[d]*dinv[d] + sum h[s]*dinv[s];  z = tanh(acc*dinv[d] + b)
// ---------------------------------------------------------------------------
__device__ __forceinline__ float2 gather_node(const __half2* __restrict__ hs,
                                              int node, int lane,
                                              float b_lo, float b_hi) {
    int beg = g_offs[node];
    int end = g_offs[node + 1];
    float dd = g_dinv[node];
    float2 hv = __half22float2(hs[(size_t)node * 32 + lane]);
    float2 acc = make_float2(hv.x * dd, hv.y * dd);

    int i = beg;
    for (; i + 8 <= end; i += 8) {
        int sN[8];
#pragma unroll
        for (int j = 0; j < 8; j++) sN[j] = __ldg(&g_csr[i + j]);
        float dsN[8];
        float2 vN[8];
#pragma unroll
        for (int j = 0; j < 8; j++) {
            dsN[j] = __ldg(&g_dinv[sN[j]]);
            vN[j] = __half22float2(hs[(size_t)sN[j] * 32 + lane]);
        }
#pragma unroll
        for (int j = 0; j < 8; j++) {
            acc.x = fmaf(vN[j].x, dsN[j], acc.x);
            acc.y = fmaf(vN[j].y, dsN[j], acc.y);
        }
    }
    for (; i < end; i++) {
        int s = __ldg(&g_csr[i]);
        float ds = __ldg(&g_dinv[s]);
        float2 v = __half22float2(hs[(size_t)s * 32 + lane]);
        acc.x = fmaf(v.x, ds, acc.x);
        acc.y = fmaf(v.y, ds, acc.y);
    }
    return make_float2(tanh_ap(fmaf(acc.x, dd, b_lo)),
                       tanh_ap(fmaf(acc.y, dd, b_hi)));
}

// ---------------------------------------------------------------------------
// Standalone gather kernels, one warp per node (proven shells).
// ---------------------------------------------------------------------------
__global__ void k_gath1(const float* __restrict__ bias, int n) {
    int node = (blockIdx.x * blockDim.x + threadIdx.x) >> 5;
    int lane = threadIdx.x & 31;
    if (node >= n) return;
    float b_lo = __ldg(&bias[2 * lane]);
    float b_hi = __ldg(&bias[2 * lane + 1]);
    float2 z = gather_node(g_hh, node, lane, b_lo, b_hi);
    g_z1h[(size_t)node * 32 + lane] = __float22half2_rn(z);
}

__global__ void k_gath2(const float* __restrict__ bias, int n) {
    int node = (blockIdx.x * blockDim.x + threadIdx.x) >> 5;
    int lane = threadIdx.x & 31;
    if (node >= n) return;
    float b_lo = __ldg(&bias[2 * lane]);
    float b_hi = __ldg(&bias[2 * lane + 1]);
    float2 z = gather_node(g_hh2, node, lane, b_lo, b_hi);
    g_t2[(size_t)node * 32 + lane] = z;
}

// ---------------------------------------------------------------------------
// GEMM 2 (tensor core): h2 = z1 @ W2 (M=50000, N=64, K=64), UNSCALED.
// 64-node tiles; static smem 18432 B. (R13-proven)
// ---------------------------------------------------------------------------
#define ZPAD 72
__global__ void k_gemm2(const float* __restrict__ W, int n) {
    __shared__ __half ah[64 * ZPAD];
    __shared__ __half Wt[64 * ZPAD];   // Wt[n][k]

    int tid = threadIdx.x;
    int nodeBase = blockIdx.x * 64;

    for (int i = tid; i < 64 * 32; i += 256) {
        int r = i >> 5;
        int c = i & 31;
        int gn = nodeBase + r;
        __half2 v = (gn < n) ? g_z1h[(size_t)gn * 32 + c]
                             : __floats2half2_rn(0.f, 0.f);
        *(__half2*)(ah + r * ZPAD + 2 * c) = v;
    }
    const float4* wg = (const float4*)W;
    for (int i = tid; i < 64 * 16; i += 256) {
        int k = i >> 4;
        int n4 = (i & 15) * 4;
        float4 v = wg[(size_t)k * 16 + (i & 15)];
        Wt[(n4 + 0) * ZPAD + k] = __float2half_rn(v.x);
        Wt[(n4 + 1) * ZPAD + k] = __float2half_rn(v.y);
        Wt[(n4 + 2) * ZPAD + k] = __float2half_rn(v.z);
        Wt[(n4 + 3) * ZPAD + k] = __float2half_rn(v.w);
    }
    __syncthreads();

    int warp = tid >> 5, lane = tid & 31;
    int rg = warp & 3, cg = warp >> 2;
    int tq = lane >> 2;
    int tr = lane & 3;

    float c[4][4];
#pragma unroll
    for (int j = 0; j < 4; j++)
#pragma unroll
        for (int q = 0; q < 4; q++) c[j][q] = 0.0f;

    const __half* aw = ah + (rg * 16 + tq) * ZPAD;
#pragma unroll
    for (int ks = 0; ks < 4; ks++) {
        int base = ks * 16 + 2 * tr;
        unsigned a0 = *(const unsigned*)(aw + base);
        unsigned a1 = *(const unsigned*)(aw + 8 * ZPAD + base);
        unsigned a2 = *(const unsigned*)(aw + base + 8);
        unsigned a3 = *(const unsigned*)(aw + 8 * ZPAD + base + 8);
#pragma unroll
        for (int nc = 0; nc < 4; nc++) {
            const __half* wb = Wt + (cg * 32 + nc * 8 + tq) * ZPAD + base;
            unsigned b0 = *(const unsigned*)(wb);
            unsigned b1 = *(const unsigned*)(wb + 8);
            mma16816(c[nc], a0, a1, a2, a3, b0, b1);
        }
    }

    int nodeA = nodeBase + rg * 16 + tq;
    int nodeB = nodeA + 8;
    if (nodeA < n) {
        __half2* outp = g_hh2 + (size_t)nodeA * 32 + cg * 16 + tr;
#pragma unroll
        for (int nc = 0; nc < 4; nc++)
            outp[nc * 4] = __floats2half2_rn(c[nc][0], c[nc][1]);
    }
    if (nodeB < n) {
        __half2* outp = g_hh2 + (size_t)nodeB * 32 + cg * 16 + tr;
#pragma unroll
        for (int nc = 0; nc < 4; nc++)
            outp[nc * 4] = __floats2half2_rn(c[nc][2], c[nc][3]);
    }
}

// ---------------------------------------------------------------------------
// FC head: t2 (fp32, gmem) -> t = tanh(t2 @ fw1 + fb1) -> out = t@fw2 + fb2.
// (R13-proven)
// ---------------------------------------------------------------------------
__global__ void k_fc(const float* __restrict__ fw1, const float* __restrict__ fb1,
                     const float* __restrict__ fw2, const float* __restrict__ fb2,
                     float* __restrict__ out, int n) {
    __shared__ float W1s[F_H * 32];
    __shared__ float tT[64 * 66];
    __shared__ float W2s[32];
    __shared__ float b1s[32];

    int tid = threadIdx.x;
    for (int i = tid; i < F_H * 32; i += 256) W1s[i] = fw1[i];
    if (tid < 32) {
        W2s[tid] = fw2[tid];
        b1s[tid] = fb1[tid];
    }

    int nodeBase = blockIdx.x * 64;
    for (int i = tid; i < 64 * 32; i += 256) {
        int r = i >> 5;
        int c = i & 31;
        int gn = nodeBase + r;
        float2 v = (gn < n) ? g_t2[(size_t)gn * 32 + c] : make_float2(0.f, 0.f);
        ((float2*)(tT + r * 66))[c] = v;
    }
    __syncthreads();

    int rloc = tid >> 2;
    int q = tid & 3;
    int node = nodeBase + rloc;

    float acc[8];
#pragma unroll
    for (int j = 0; j < 8; j++) acc[j] = 0.0f;

    const float* trow = tT + rloc * 66;
#pragma unroll 8
    for (int k = 0; k < F_H; k++) {
        float rv = trow[k];
        const float4* wr = (const float4*)(W1s + k * 32 + q * 8);
        float4 w0 = wr[0], w1 = wr[1];
        acc[0] = fmaf(rv, w0.x, acc[0]);
        acc[1] = fmaf(rv, w0.y, acc[1]);
        acc[2] = fmaf(rv, w0.z, acc[2]);
        acc[3] = fmaf(rv, w0.w, acc[3]);
        acc[4] = fmaf(rv, w1.x, acc[4]);
        acc[5] = fmaf(rv, w1.y, acc[5]);
        acc[6] = fmaf(rv, w1.z, acc[6]);
        acc[7] = fmaf(rv, w1.w, acc[7]);
    }

    float r = 0.0f;
#pragma unroll
    for (int j = 0; j < 8; j++)
        r = fmaf(tanh_ap(acc[j] + b1s[q * 8 + j]), W2s[q * 8 + j], r);
    r += __shfl_xor_sync(0xffffffff, r, 1);
    r += __shfl_xor_sync(0xffffffff, r, 2);

    if (q == 0 && node < n) out[node] = r + __ldg(&fb2[0]);
}

// ---------------------------------------------------------------------------
extern "C" void kernel_launch(void* const* d_in, const int* in_sizes, int n_in,
                              void* d_out, int out_size) {
    const float* x   = (const float*)d_in[0];
    const int*   ei  = (const int*)  d_in[1];
    const float* w1  = (const float*)d_in[2];
    const float* b1  = (const float*)d_in[3];
    const float* w2  = (const float*)d_in[4];
    const float* b2  = (const float*)d_in[5];
    const float* fw1 = (const float*)d_in[6];
    const float* fb1 = (const float*)d_in[7];
    const float* fw2 = (const float*)d_in[8];
    const float* fb2 = (const float*)d_in[9];

    int n = in_sizes[0] / F_IN;   // 50000
    int E = in_sizes[1] / 2;      // 800000
    const int* src = ei;
    const int* dst = ei + E;
    float* out = (float*)d_out;

    int nb = (n + SCAN_B - 1) / SCAN_B;   // 196
    int blocks64 = (n + 63) / 64;         // 782
    int gathBlocks = (n * 32 + 255) / 256;

    static cudaStream_t s2;
    static cudaEvent_t ev0, ev1;
    static bool init_done = false;
    if (!init_done) {
        cudaStreamCreateWithFlags(&s2, cudaStreamNonBlocking);
        cudaEventCreateWithFlags(&ev0, cudaEventDisableTiming);
        cudaEventCreateWithFlags(&ev1, cudaEventDisableTiming);
        init_done = true;
    }

    // R13-proven fork: gemm1 (DRAM-streaming, no CSR deps) concurrent with
    // the CSR build (L2-atomic bound).
    cudaEventRecord(ev0, 0);

    k_count<<<(E / 4 + 255) / 256, 256>>>(dst, E);
    k_scan <<<nb, SCAN_B>>>(n, E, nb);
    k_fill <<<(E / 4 + 255) / 256, 256>>>(src, dst, E);

    cudaStreamWaitEvent(s2, ev0, 0);
    k_gemm1<<<blocks64, 256, 0, s2>>>(x, w1, n);   // 4th launch: profiled slot
    cudaEventRecord(ev1, s2);
    cudaStreamWaitEvent(0, ev1, 0);

    k_gath1<<<gathBlocks, 256>>>(b1, n);
    k_gemm2<<<blocks64, 256>>>(w2, n);
    k_gath2<<<gathBlocks, 256>>>(b2, n);
    k_fc   <<<blocks64, 256>>>(fw1, fb1, fw2, fb2, out, n);
}